// round 16
// baseline (speedup 1.0000x reference)
#include <cuda_runtime.h>

#define DEV __device__ __forceinline__

constexpr int B    = 8;
constexpr int N    = 8192;
constexpr int M    = 2500;
constexpr int SPP  = 250;    // M / P(=10)

// joint tile: 64 queries x 1024 candidates per block (CPT=8), ILP=2 queries/iter
constexpr int QCH   = 40;              // query chunks (40*64 = 2560 >= 2500)
constexpr int QPB2  = 64;              // queries per block
constexpr int GCH   = 8;               // gt chunks per batch (8*1024 = 8192)
constexpr int CPT   = 8;               // candidates per thread (4 packs)
constexpr int CPW   = 32 * CPT;        // 256 candidates per warp
constexpr int NBLK_C = B * QCH * GCH;  // 2560 chamfer blocks

// k_finish decomposition
constexpr int FT    = 128;
constexpr int BM4   = (B * M) / 4;              // 5000 uint4 (P side)
constexpr int BN4   = (B * N) / 4;              // 16384 uint4 (G side)
constexpr int FB_F  = 20 * B;                   // 160 fff blocks
constexpr int FB_P  = (BM4 + FT - 1) / FT;      // 40
constexpr int FB_G  = BN4 / FT;                 // 128
constexpr int FB_T  = FB_F + FB_P + FB_G;       // 328

constexpr float    BIG  = 3.2e38f;
constexpr unsigned INFB = 0x7F800000u;          // +inf bits (max for nonneg floats)

// Global min arrays (nonneg d^2 -> raw uint bit pattern preserves order).
__device__ unsigned g_minP[B * M];
__device__ unsigned g_minG[B * N];
__device__ float    g_fffp[FB_F * 11];
__device__ float    g_sum2[FB_P + FB_G];
__device__ unsigned g_done;              // zero-init; reset by last block each launch

// ---- packed fp32x2 helpers ----
typedef unsigned long long ull;
DEV ull pack2(float lo, float hi) {
    ull r; asm("mov.b64 %0, {%1, %2};" : "=l"(r) : "f"(lo), "f"(hi)); return r;
}
DEV void unpack2(ull v, float& lo, float& hi) {
    asm("mov.b64 {%0, %1}, %2;" : "=f"(lo), "=f"(hi) : "l"(v));
}
DEV ull fma2(ull a, ull b, ull c) {
    ull d; asm("fma.rn.f32x2 %0, %1, %2, %3;" : "=l"(d) : "l"(a), "l"(b), "l"(c)); return d;
}
DEV ull add2(ull a, ull b) {
    ull d; asm("add.rn.f32x2 %0, %1, %2;" : "=l"(d) : "l"(a), "l"(b)); return d;
}

DEV float blockReduceSum(float v) {
    __shared__ float sred[32];
    #pragma unroll
    for (int o = 16; o > 0; o >>= 1) v += __shfl_down_sync(0xffffffffu, v, o);
    int lane = threadIdx.x & 31, w = threadIdx.x >> 5;
    if (lane == 0) sred[w] = v;
    __syncthreads();
    int nw = (blockDim.x + 31) >> 5;
    v = (threadIdx.x < (unsigned)nw) ? sred[threadIdx.x] : 0.0f;
    if (w == 0) {
        #pragma unroll
        for (int o = 16; o > 0; o >>= 1) v += __shfl_down_sync(0xffffffffu, v, o);
    }
    __syncthreads();
    return v;
}

// ================= K0: init min arrays =================
__global__ void __launch_bounds__(512) k_init() {
    int idx = blockIdx.x * 512 + threadIdx.x;
    if (idx < B * M) g_minP[idx] = INFB;
    int i2 = idx - B * M;
    if (i2 >= 0 && i2 < B * N) g_minG[i2] = INFB;
}

// ================= K1: pure chamfer, atomicMin epilogues =================
__global__ void __launch_bounds__(128, 6) k_mega(const float* __restrict__ pred,
                                                 const float* __restrict__ gt) {
    int bid = blockIdx.x;
    int tid = threadIdx.x;

    __shared__ ulonglong2 qs[QPB2][2];          // [0]={qx2,qy2} [1]={qz2,qn2}
    __shared__ float      rowTmp[4][QPB2 * 33]; // [warp][s*33 + lane]

    int gi = bid & (GCH - 1);
    int qi = (bid >> 3) % QCH;
    int b  = bid / (GCH * QCH);
    int w    = tid >> 5;
    int lane = tid & 31;
    int qbase = qi * QPB2;

    if (tid < QPB2) {
        int m = qbase + tid;
        float x = 0.f, y = 0.f, z = 0.f, n = BIG;
        if (m < M) {
            const float* p = pred + (size_t)(b * M + m) * 3;
            x = p[0]; y = p[1]; z = p[2];
            n = x * x + y * y + z * z;
        }
        ulonglong2 u0, u1;
        u0.x = pack2(-2.f * x, -2.f * x);
        u0.y = pack2(-2.f * y, -2.f * y);
        u1.x = pack2(-2.f * z, -2.f * z);
        u1.y = pack2(n, n);
        qs[tid][0] = u0;
        qs[tid][1] = u1;
    }

    int cbase = gi * (4 * CPW) + w * CPW + lane * CPT;
    const float4* gsrc = (const float4*)(gt + (size_t)(b * N + cbase) * 3);
    float4 f0 = gsrc[0], f1 = gsrc[1], f2 = gsrc[2];
    float4 f3 = gsrc[3], f4 = gsrc[4], f5 = gsrc[5];
    float cf[24] = {f0.x,f0.y,f0.z,f0.w, f1.x,f1.y,f1.z,f1.w,
                    f2.x,f2.y,f2.z,f2.w, f3.x,f3.y,f3.z,f3.w,
                    f4.x,f4.y,f4.z,f4.w, f5.x,f5.y,f5.z,f5.w};
    ull cx[4], cy[4], cz[4], gn[4];
    #pragma unroll
    for (int k = 0; k < 4; k++) {
        float x0 = cf[6*k+0], y0 = cf[6*k+1], z0 = cf[6*k+2];
        float x1 = cf[6*k+3], y1 = cf[6*k+4], z1 = cf[6*k+5];
        cx[k] = pack2(x0, x1);
        cy[k] = pack2(y0, y1);
        cz[k] = pack2(z0, z1);
        gn[k] = pack2(x0*x0 + y0*y0 + z0*z0, x1*x1 + y1*y1 + z1*z1);
    }
    float cm[8];
    #pragma unroll
    for (int k = 0; k < 8; k++) cm[k] = BIG;
    __syncthreads();

    #pragma unroll 2
    for (int s = 0; s < QPB2 / 2; s++) {
        ulonglong2 aA = qs[s][0],      cA = qs[s][1];
        ulonglong2 aB = qs[s + 32][0], cB = qs[s + 32][1];

        ull tA0 = fma2(cx[0], aA.x, fma2(cy[0], aA.y, fma2(cz[0], cA.x, cA.y)));
        ull tB0 = fma2(cx[0], aB.x, fma2(cy[0], aB.y, fma2(cz[0], cB.x, cB.y)));
        ull tA1 = fma2(cx[1], aA.x, fma2(cy[1], aA.y, fma2(cz[1], cA.x, cA.y)));
        ull tB1 = fma2(cx[1], aB.x, fma2(cy[1], aB.y, fma2(cz[1], cB.x, cB.y)));
        ull tA2 = fma2(cx[2], aA.x, fma2(cy[2], aA.y, fma2(cz[2], cA.x, cA.y)));
        ull tB2 = fma2(cx[2], aB.x, fma2(cy[2], aB.y, fma2(cz[2], cB.x, cB.y)));
        ull tA3 = fma2(cx[3], aA.x, fma2(cy[3], aA.y, fma2(cz[3], cA.x, cA.y)));
        ull tB3 = fma2(cx[3], aB.x, fma2(cy[3], aB.y, fma2(cz[3], cB.x, cB.y)));

        float l, h;
        unpack2(tA0, l, h); cm[0] = fminf(cm[0], l); cm[1] = fminf(cm[1], h);
        unpack2(tB0, l, h); cm[0] = fminf(cm[0], l); cm[1] = fminf(cm[1], h);
        unpack2(tA1, l, h); cm[2] = fminf(cm[2], l); cm[3] = fminf(cm[3], h);
        unpack2(tB1, l, h); cm[2] = fminf(cm[2], l); cm[3] = fminf(cm[3], h);
        unpack2(tA2, l, h); cm[4] = fminf(cm[4], l); cm[5] = fminf(cm[5], h);
        unpack2(tB2, l, h); cm[4] = fminf(cm[4], l); cm[5] = fminf(cm[5], h);
        unpack2(tA3, l, h); cm[6] = fminf(cm[6], l); cm[7] = fminf(cm[7], h);
        unpack2(tB3, l, h); cm[6] = fminf(cm[6], l); cm[7] = fminf(cm[7], h);

        {
            float r0l, r0h, r1l, r1h, r2l, r2h, r3l, r3h;
            unpack2(add2(tA0, gn[0]), r0l, r0h);
            unpack2(add2(tA1, gn[1]), r1l, r1h);
            unpack2(add2(tA2, gn[2]), r2l, r2h);
            unpack2(add2(tA3, gn[3]), r3l, r3h);
            float rv = fminf(fminf(fminf(r0l, r0h), fminf(r1l, r1h)),
                             fminf(fminf(r2l, r2h), fminf(r3l, r3h)));
            rowTmp[w][s * 33 + lane] = rv;
        }
        {
            float r0l, r0h, r1l, r1h, r2l, r2h, r3l, r3h;
            unpack2(add2(tB0, gn[0]), r0l, r0h);
            unpack2(add2(tB1, gn[1]), r1l, r1h);
            unpack2(add2(tB2, gn[2]), r2l, r2h);
            unpack2(add2(tB3, gn[3]), r3l, r3h);
            float rv = fminf(fminf(fminf(r0l, r0h), fminf(r1l, r1h)),
                             fminf(fminf(r2l, r2h), fminf(r3l, r3h)));
            rowTmp[w][(s + 32) * 33 + lane] = rv;
        }
    }

    // col epilogue: clamp, atomicMin (coalesced: 8 consecutive per thread)
    {
        float n0, n1, n2, n3, n4, n5, n6, n7;
        unpack2(gn[0], n0, n1); unpack2(gn[1], n2, n3);
        unpack2(gn[2], n4, n5); unpack2(gn[3], n6, n7);
        unsigned* outg = g_minG + b * N + cbase;
        atomicMin(&outg[0], __float_as_uint(fmaxf(cm[0] + n0, 0.f)));
        atomicMin(&outg[1], __float_as_uint(fmaxf(cm[1] + n1, 0.f)));
        atomicMin(&outg[2], __float_as_uint(fmaxf(cm[2] + n2, 0.f)));
        atomicMin(&outg[3], __float_as_uint(fmaxf(cm[3] + n3, 0.f)));
        atomicMin(&outg[4], __float_as_uint(fmaxf(cm[4] + n4, 0.f)));
        atomicMin(&outg[5], __float_as_uint(fmaxf(cm[5] + n5, 0.f)));
        atomicMin(&outg[6], __float_as_uint(fmaxf(cm[6] + n6, 0.f)));
        atomicMin(&outg[7], __float_as_uint(fmaxf(cm[7] + n7, 0.f)));
    }
    __syncthreads();

    // row epilogue: reduce 32 lanes per query, clamp, atomicMin
    for (int idx = tid; idx < 4 * QPB2; idx += 128) {
        int ww = idx >> 6;
        int s  = idx & (QPB2 - 1);
        const float* src = &rowTmp[ww][s * 33];
        float f = src[0];
        #pragma unroll
        for (int l2 = 1; l2 < 32; l2++) f = fminf(f, src[l2]);
        int m = qbase + s;
        if (m < M)
            atomicMin(&g_minP[b * M + m], __float_as_uint(fmaxf(f, 0.f)));
    }
}

// ====== K2: finish — fff partials + decode/sum mins; LAST block combines =====
__global__ void __launch_bounds__(FT) k_finish(const float* __restrict__ fff,
                                               const float* __restrict__ A_gt,
                                               float* __restrict__ out) {
    int bid = blockIdx.x;
    int tid = threadIdx.x;
    __shared__ unsigned sLast;

    if (bid < FB_F) {
        int b = bid / 20;
        int m = (bid % 20) * FT + tid;
        float v[11];
        #pragma unroll
        for (int i = 0; i < 11; i++) v[i] = 0.0f;
        if (m < M) {
            int idx = (b * M + m) * 3;
            float E = fff[idx], F = fff[idx + 1], G = fff[idx + 2];
            float A2  = fmaxf(E * G - F * F, 0.0f);
            float A   = sqrtf(A2);
            float inv = 1.0f / (A2 + 1e-20f);
            v[0] = E;        v[1] = G;        v[2] = inv;
            v[3] = E * inv;  v[4] = E * E * inv;
            v[5] = G * inv;  v[6] = G * G * inv;
            v[7] = F * F * inv;
            float d = E - G; v[8] = d * d * inv;
            if ((b & 1) == 0) {
                int idx2 = ((b + 1) * M + m) * 3;
                float E2 = fff[idx2], F2 = fff[idx2 + 1], G2 = fff[idx2 + 2];
                float dE = E - E2, dF = F - F2, dG = G - G2;
                v[9] = dE * dE + 2.0f * dF * dF + dG * dG;
            }
            v[10] = A;
        }
        #pragma unroll
        for (int k = 0; k < 11; k++) {
            float s = blockReduceSum(v[k]);
            if (tid == 0) g_fffp[bid * 11 + k] = s;
        }
    } else {
        int fb = bid - FB_F;
        float d = 0.0f;
        if (fb < FB_P) {
            int e = fb * FT + tid;          // [0, BM4)
            if (e < BM4) {
                uint4 u = ((const uint4*)g_minP)[e];
                d = __uint_as_float(u.x) + __uint_as_float(u.y)
                  + __uint_as_float(u.z) + __uint_as_float(u.w);
            }
        } else {
            int e = (fb - FB_P) * FT + tid;  // [0, BN4), exact
            uint4 u = ((const uint4*)g_minG)[e];
            d = __uint_as_float(u.x) + __uint_as_float(u.y)
              + __uint_as_float(u.z) + __uint_as_float(u.w);
        }
        float s = blockReduceSum(d);
        if (tid == 0) g_sum2[fb] = s;
    }

    // last-block-does-final
    __threadfence();
    if (tid == 0) sLast = (atomicAdd(&g_done, 1u) == (unsigned)(FB_T - 1));
    __syncthreads();
    if (!sLast) return;
    __threadfence();   // acquire

    __shared__ float sA[FB_F];
    __shared__ float acc2[12];
    #pragma unroll
    for (int k = 0; k < 10; k++) {
        float v = 0.0f;
        for (int j = tid; j < FB_F; j += FT) v += g_fffp[j * 11 + k];
        float s = blockReduceSum(v);
        if (tid == 0) acc2[k] = s;
    }
    {
        float v = 0.0f;
        for (int j = tid; j < FB_P; j += FT) v += g_sum2[j];
        float s = blockReduceSum(v);
        if (tid == 0) acc2[10] = s;
        v = 0.0f;
        for (int j = tid; j < FB_G; j += FT) v += g_sum2[FB_P + j];
        s = blockReduceSum(v);
        if (tid == 0) acc2[11] = s;
    }
    for (int j = tid; j < FB_F; j += FT) sA[j] = g_fffp[j * 11 + 10];
    __syncthreads();

    if (tid == 0) {
        float BM = (float)(B * M);
        float L_chd = acc2[10] / BM + acc2[11] / (float)(B * N);
        float sE = acc2[0], sG = acc2[1], sInv = acc2[2];
        float sEinv = acc2[3], sE2inv = acc2[4], sGinv = acc2[5], sG2inv = acc2[6];
        float sF2inv = acc2[7], sStretch = acc2[8], sMc = acc2[9];
        float mE = sE / BM, mG = sG / BM;
        float L_E  = (sE2inv - 2.0f * mE * sEinv + mE * mE * sInv) / BM;
        float L_G  = (sG2inv - 2.0f * mG * sGinv + mG * mG * sInv) / BM;
        float L_F  = sF2inv  / BM;
        float L_st = sStretch / BM;
        float L_mc = sMc / (0.5f * BM);
        float L_ol = 0.0f;
        for (int b = 0; b < B; b++) {
            float at = 0.0f;
            for (int j = 0; j < 20; j++) at += sA[b * 20 + j];
            at *= (1.0f / (float)SPP);
            float r = fmaxf(at - A_gt[b], 0.0f);
            L_ol += r * r;
        }
        L_ol *= (1.0f / (float)B);
        out[0] = L_chd + L_mc + L_F + L_E + L_G + L_st + L_ol;
        g_done = 0;   // reset for next launch/replay
    }
}

extern "C" void kernel_launch(void* const* d_in, const int* in_sizes, int n_in,
                              void* d_out, int out_size) {
    (void)in_sizes; (void)n_in; (void)out_size;
    const float* pc_gt   = (const float*)d_in[0];
    const float* pc_pred = (const float*)d_in[1];
    const float* fffp    = (const float*)d_in[2];
    const float* A_gt    = (const float*)d_in[3];
    float* out = (float*)d_out;

    k_init  <<<(B * M + B * N + 511) / 512, 512>>>();
    k_mega  <<<NBLK_C, 128>>>(pc_pred, pc_gt);
    k_finish<<<FB_T, FT>>>(fffp, A_gt, out);
}

// round 17
// speedup vs baseline: 1.0332x; 1.0332x over previous
#include <cuda_runtime.h>

#define DEV __device__ __forceinline__

constexpr int B    = 8;
constexpr int N    = 8192;
constexpr int M    = 2500;
constexpr int SPP  = 250;    // M / P(=10)

// joint tile: 64 queries x 1024 candidates per block (CPT=8), ILP=2 queries/iter
constexpr int QCH   = 40;              // query chunks (40*64 = 2560 >= 2500)
constexpr int QPB2  = 64;              // queries per block
constexpr int GCH   = 8;               // gt chunks per batch (8*1024 = 8192)
constexpr int CPT   = 8;               // candidates per thread (4 packs)
constexpr int CPW   = 32 * CPT;        // 256 candidates per warp
constexpr int WCH   = N / CPW;         // 32 warp-level candidate chunks
constexpr int NBLK_C = B * QCH * GCH;  // 2560 chamfer blocks

// k_finish decomposition: reduction blocks = 16 elements x 8 chunk-groups
constexpr int FT    = 128;
constexpr int BM4   = (B * M) / 4;              // 5000 float4 (P side)
constexpr int BN4   = (B * N) / 4;              // 16384 float4 (G side)
constexpr int FB_F  = 20 * B;                   // 160 fff blocks
constexpr int FB_P  = (BM4 + 15) / 16;          // 313 (16 elems/block)
constexpr int FB_G  = BN4 / 16;                 // 1024
constexpr int FB_T  = FB_F + FB_P + FB_G;       // 1497

constexpr float BIG = 3.2e38f;

// Partials — every slot written unconditionally; no init kernel, no atomics on data.
__device__ float    g_rowPart[(size_t)WCH * B * M];   // 2.56 MB
__device__ float    g_colPart[(size_t)QCH * B * N];   // 10.5 MB
__device__ float    g_fffp[FB_F * 11];
__device__ float    g_sum2[FB_P + FB_G];
__device__ unsigned g_done;              // zero-init; reset by last block each launch

// ---- packed fp32x2 helpers ----
typedef unsigned long long ull;
DEV ull pack2(float lo, float hi) {
    ull r; asm("mov.b64 %0, {%1, %2};" : "=l"(r) : "f"(lo), "f"(hi)); return r;
}
DEV void unpack2(ull v, float& lo, float& hi) {
    asm("mov.b64 {%0, %1}, %2;" : "=f"(lo), "=f"(hi) : "l"(v));
}
DEV ull fma2(ull a, ull b, ull c) {
    ull d; asm("fma.rn.f32x2 %0, %1, %2, %3;" : "=l"(d) : "l"(a), "l"(b), "l"(c)); return d;
}
DEV ull add2(ull a, ull b) {
    ull d; asm("add.rn.f32x2 %0, %1, %2;" : "=l"(d) : "l"(a), "l"(b)); return d;
}
DEV float4 min4(float4 a, float4 b) {
    return make_float4(fminf(a.x, b.x), fminf(a.y, b.y),
                       fminf(a.z, b.z), fminf(a.w, b.w));
}

DEV float blockReduceSum(float v) {
    __shared__ float sred[32];
    #pragma unroll
    for (int o = 16; o > 0; o >>= 1) v += __shfl_down_sync(0xffffffffu, v, o);
    int lane = threadIdx.x & 31, w = threadIdx.x >> 5;
    if (lane == 0) sred[w] = v;
    __syncthreads();
    int nw = (blockDim.x + 31) >> 5;
    v = (threadIdx.x < (unsigned)nw) ? sred[threadIdx.x] : 0.0f;
    if (w == 0) {
        #pragma unroll
        for (int o = 16; o > 0; o >>= 1) v += __shfl_down_sync(0xffffffffu, v, o);
    }
    __syncthreads();
    return v;
}

// ================= K1: pure chamfer (identical to R15 best) =================
__global__ void __launch_bounds__(128, 6) k_mega(const float* __restrict__ pred,
                                                 const float* __restrict__ gt) {
    int bid = blockIdx.x;
    int tid = threadIdx.x;

    __shared__ ulonglong2 qs[QPB2][2];
    __shared__ float      rowTmp[4][QPB2 * 33];

    int gi = bid & (GCH - 1);
    int qi = (bid >> 3) % QCH;
    int b  = bid / (GCH * QCH);
    int w    = tid >> 5;
    int lane = tid & 31;
    int qbase = qi * QPB2;

    if (tid < QPB2) {
        int m = qbase + tid;
        float x = 0.f, y = 0.f, z = 0.f, n = BIG;
        if (m < M) {
            const float* p = pred + (size_t)(b * M + m) * 3;
            x = p[0]; y = p[1]; z = p[2];
            n = x * x + y * y + z * z;
        }
        ulonglong2 u0, u1;
        u0.x = pack2(-2.f * x, -2.f * x);
        u0.y = pack2(-2.f * y, -2.f * y);
        u1.x = pack2(-2.f * z, -2.f * z);
        u1.y = pack2(n, n);
        qs[tid][0] = u0;
        qs[tid][1] = u1;
    }

    int cbase = gi * (4 * CPW) + w * CPW + lane * CPT;
    const float4* gsrc = (const float4*)(gt + (size_t)(b * N + cbase) * 3);
    float4 f0 = gsrc[0], f1 = gsrc[1], f2 = gsrc[2];
    float4 f3 = gsrc[3], f4 = gsrc[4], f5 = gsrc[5];
    float cf[24] = {f0.x,f0.y,f0.z,f0.w, f1.x,f1.y,f1.z,f1.w,
                    f2.x,f2.y,f2.z,f2.w, f3.x,f3.y,f3.z,f3.w,
                    f4.x,f4.y,f4.z,f4.w, f5.x,f5.y,f5.z,f5.w};
    ull cx[4], cy[4], cz[4], gn[4];
    #pragma unroll
    for (int k = 0; k < 4; k++) {
        float x0 = cf[6*k+0], y0 = cf[6*k+1], z0 = cf[6*k+2];
        float x1 = cf[6*k+3], y1 = cf[6*k+4], z1 = cf[6*k+5];
        cx[k] = pack2(x0, x1);
        cy[k] = pack2(y0, y1);
        cz[k] = pack2(z0, z1);
        gn[k] = pack2(x0*x0 + y0*y0 + z0*z0, x1*x1 + y1*y1 + z1*z1);
    }
    float cm[8];
    #pragma unroll
    for (int k = 0; k < 8; k++) cm[k] = BIG;
    __syncthreads();

    #pragma unroll 2
    for (int s = 0; s < QPB2 / 2; s++) {
        ulonglong2 aA = qs[s][0],      cA = qs[s][1];
        ulonglong2 aB = qs[s + 32][0], cB = qs[s + 32][1];

        ull tA0 = fma2(cx[0], aA.x, fma2(cy[0], aA.y, fma2(cz[0], cA.x, cA.y)));
        ull tB0 = fma2(cx[0], aB.x, fma2(cy[0], aB.y, fma2(cz[0], cB.x, cB.y)));
        ull tA1 = fma2(cx[1], aA.x, fma2(cy[1], aA.y, fma2(cz[1], cA.x, cA.y)));
        ull tB1 = fma2(cx[1], aB.x, fma2(cy[1], aB.y, fma2(cz[1], cB.x, cB.y)));
        ull tA2 = fma2(cx[2], aA.x, fma2(cy[2], aA.y, fma2(cz[2], cA.x, cA.y)));
        ull tB2 = fma2(cx[2], aB.x, fma2(cy[2], aB.y, fma2(cz[2], cB.x, cB.y)));
        ull tA3 = fma2(cx[3], aA.x, fma2(cy[3], aA.y, fma2(cz[3], cA.x, cA.y)));
        ull tB3 = fma2(cx[3], aB.x, fma2(cy[3], aB.y, fma2(cz[3], cB.x, cB.y)));

        float l, h;
        unpack2(tA0, l, h); cm[0] = fminf(cm[0], l); cm[1] = fminf(cm[1], h);
        unpack2(tB0, l, h); cm[0] = fminf(cm[0], l); cm[1] = fminf(cm[1], h);
        unpack2(tA1, l, h); cm[2] = fminf(cm[2], l); cm[3] = fminf(cm[3], h);
        unpack2(tB1, l, h); cm[2] = fminf(cm[2], l); cm[3] = fminf(cm[3], h);
        unpack2(tA2, l, h); cm[4] = fminf(cm[4], l); cm[5] = fminf(cm[5], h);
        unpack2(tB2, l, h); cm[4] = fminf(cm[4], l); cm[5] = fminf(cm[5], h);
        unpack2(tA3, l, h); cm[6] = fminf(cm[6], l); cm[7] = fminf(cm[7], h);
        unpack2(tB3, l, h); cm[6] = fminf(cm[6], l); cm[7] = fminf(cm[7], h);

        {
            float r0l, r0h, r1l, r1h, r2l, r2h, r3l, r3h;
            unpack2(add2(tA0, gn[0]), r0l, r0h);
            unpack2(add2(tA1, gn[1]), r1l, r1h);
            unpack2(add2(tA2, gn[2]), r2l, r2h);
            unpack2(add2(tA3, gn[3]), r3l, r3h);
            float rv = fminf(fminf(fminf(r0l, r0h), fminf(r1l, r1h)),
                             fminf(fminf(r2l, r2h), fminf(r3l, r3h)));
            rowTmp[w][s * 33 + lane] = rv;
        }
        {
            float r0l, r0h, r1l, r1h, r2l, r2h, r3l, r3h;
            unpack2(add2(tB0, gn[0]), r0l, r0h);
            unpack2(add2(tB1, gn[1]), r1l, r1h);
            unpack2(add2(tB2, gn[2]), r2l, r2h);
            unpack2(add2(tB3, gn[3]), r3l, r3h);
            float rv = fminf(fminf(fminf(r0l, r0h), fminf(r1l, r1h)),
                             fminf(fminf(r2l, r2h), fminf(r3l, r3h)));
            rowTmp[w][(s + 32) * 33 + lane] = rv;
        }
    }

    {
        float n0, n1, n2, n3, n4, n5, n6, n7;
        unpack2(gn[0], n0, n1); unpack2(gn[1], n2, n3);
        unpack2(gn[2], n4, n5); unpack2(gn[3], n6, n7);
        float4* outc = (float4*)(g_colPart + (size_t)qi * (B * N) + b * N + cbase);
        outc[0] = make_float4(fmaxf(cm[0] + n0, 0.f), fmaxf(cm[1] + n1, 0.f),
                              fmaxf(cm[2] + n2, 0.f), fmaxf(cm[3] + n3, 0.f));
        outc[1] = make_float4(fmaxf(cm[4] + n4, 0.f), fmaxf(cm[5] + n5, 0.f),
                              fmaxf(cm[6] + n6, 0.f), fmaxf(cm[7] + n7, 0.f));
    }
    __syncthreads();

    for (int idx = tid; idx < 4 * QPB2; idx += 128) {
        int ww = idx >> 6;
        int s  = idx & (QPB2 - 1);
        const float* src = &rowTmp[ww][s * 33];
        float f = src[0];
        #pragma unroll
        for (int l2 = 1; l2 < 32; l2++) f = fminf(f, src[l2]);
        int m = qbase + s;
        if (m < M) {
            int ch = gi * 4 + ww;
            g_rowPart[(size_t)ch * (B * M) + b * M + m] = f;
        }
    }
}

// ====== K2: finish — chunk-parallel reductions; LAST block does final combine =====
__global__ void __launch_bounds__(FT) k_finish(const float* __restrict__ fff,
                                               const float* __restrict__ A_gt,
                                               float* __restrict__ out) {
    int bid = blockIdx.x;
    int tid = threadIdx.x;
    __shared__ unsigned sLast;

    if (bid < FB_F) {
        int b = bid / 20;
        int m = (bid % 20) * FT + tid;
        float v[11];
        #pragma unroll
        for (int i = 0; i < 11; i++) v[i] = 0.0f;
        if (m < M) {
            int idx = (b * M + m) * 3;
            float E = fff[idx], F = fff[idx + 1], G = fff[idx + 2];
            float A2  = fmaxf(E * G - F * F, 0.0f);
            float A   = sqrtf(A2);
            float inv = 1.0f / (A2 + 1e-20f);
            v[0] = E;        v[1] = G;        v[2] = inv;
            v[3] = E * inv;  v[4] = E * E * inv;
            v[5] = G * inv;  v[6] = G * G * inv;
            v[7] = F * F * inv;
            float d = E - G; v[8] = d * d * inv;
            if ((b & 1) == 0) {
                int idx2 = ((b + 1) * M + m) * 3;
                float E2 = fff[idx2], F2 = fff[idx2 + 1], G2 = fff[idx2 + 2];
                float dE = E - E2, dF = F - F2, dG = G - G2;
                v[9] = dE * dE + 2.0f * dF * dF + dG * dG;
            }
            v[10] = A;
        }
        #pragma unroll
        for (int k = 0; k < 11; k++) {
            float s = blockReduceSum(v[k]);
            if (tid == 0) g_fffp[bid * 11 + k] = s;
        }
    } else {
        // chunk-parallel min reduction: 16 elements x 8 chunk-groups per block
        __shared__ float4 sm[8][16];
        int fb  = bid - FB_F;
        int ex  = tid & 15;        // element within block
        int grp = tid >> 4;        // chunk group [0,8)
        float d = 0.0f;

        if (fb < FB_P) {
            // P side: rowPart, WCH=32 chunks -> 4 per group
            int e = fb * 16 + ex;  // [0, BM4)
            float4 acc = make_float4(BIG, BIG, BIG, BIG);
            if (e < BM4) {
                const float4* rp = (const float4*)g_rowPart;
                float4 v0 = rp[(size_t)(grp * 4 + 0) * BM4 + e];
                float4 v1 = rp[(size_t)(grp * 4 + 1) * BM4 + e];
                float4 v2 = rp[(size_t)(grp * 4 + 2) * BM4 + e];
                float4 v3 = rp[(size_t)(grp * 4 + 3) * BM4 + e];
                acc = min4(min4(v0, v1), min4(v2, v3));
            }
            sm[grp][ex] = acc;
            __syncthreads();
            if (grp == 0 && e < BM4) {
                float4 f = sm[0][ex];
                #pragma unroll
                for (int g = 1; g < 8; g++) f = min4(f, sm[g][ex]);
                d = fmaxf(f.x, 0.f) + fmaxf(f.y, 0.f)
                  + fmaxf(f.z, 0.f) + fmaxf(f.w, 0.f);
            }
        } else {
            // G side: colPart, QCH=40 chunks -> 5 per group
            int e = (fb - FB_P) * 16 + ex;  // [0, BN4), exact
            const float4* cp = (const float4*)g_colPart;
            float4 v0 = cp[(size_t)(grp * 5 + 0) * BN4 + e];
            float4 v1 = cp[(size_t)(grp * 5 + 1) * BN4 + e];
            float4 v2 = cp[(size_t)(grp * 5 + 2) * BN4 + e];
            float4 v3 = cp[(size_t)(grp * 5 + 3) * BN4 + e];
            float4 v4 = cp[(size_t)(grp * 5 + 4) * BN4 + e];
            float4 acc = min4(min4(min4(v0, v1), min4(v2, v3)), v4);
            sm[grp][ex] = acc;
            __syncthreads();
            if (grp == 0) {
                float4 f = sm[0][ex];
                #pragma unroll
                for (int g = 1; g < 8; g++) f = min4(f, sm[g][ex]);
                d = f.x + f.y + f.z + f.w;   // already clamped at write
            }
        }
        float s = blockReduceSum(d);
        if (tid == 0) g_sum2[fb] = s;
    }

    // last-block-does-final
    __threadfence();
    if (tid == 0) sLast = (atomicAdd(&g_done, 1u) == (unsigned)(FB_T - 1));
    __syncthreads();
    if (!sLast) return;
    __threadfence();   // acquire

    __shared__ float sA[FB_F];
    __shared__ float acc2[12];
    #pragma unroll
    for (int k = 0; k < 10; k++) {
        float v = 0.0f;
        for (int j = tid; j < FB_F; j += FT) v += g_fffp[j * 11 + k];
        float s = blockReduceSum(v);
        if (tid == 0) acc2[k] = s;
    }
    {
        float v = 0.0f;
        for (int j = tid; j < FB_P; j += FT) v += g_sum2[j];
        float s = blockReduceSum(v);
        if (tid == 0) acc2[10] = s;
        v = 0.0f;
        for (int j = tid; j < FB_G; j += FT) v += g_sum2[FB_P + j];
        s = blockReduceSum(v);
        if (tid == 0) acc2[11] = s;
    }
    for (int j = tid; j < FB_F; j += FT) sA[j] = g_fffp[j * 11 + 10];
    __syncthreads();

    if (tid == 0) {
        float BM = (float)(B * M);
        float L_chd = acc2[10] / BM + acc2[11] / (float)(B * N);
        float sE = acc2[0], sG = acc2[1], sInv = acc2[2];
        float sEinv = acc2[3], sE2inv = acc2[4], sGinv = acc2[5], sG2inv = acc2[6];
        float sF2inv = acc2[7], sStretch = acc2[8], sMc = acc2[9];
        float mE = sE / BM, mG = sG / BM;
        float L_E  = (sE2inv - 2.0f * mE * sEinv + mE * mE * sInv) / BM;
        float L_G  = (sG2inv - 2.0f * mG * sGinv + mG * mG * sInv) / BM;
        float L_F  = sF2inv  / BM;
        float L_st = sStretch / BM;
        float L_mc = sMc / (0.5f * BM);
        float L_ol = 0.0f;
        for (int b = 0; b < B; b++) {
            float at = 0.0f;
            for (int j = 0; j < 20; j++) at += sA[b * 20 + j];
            at *= (1.0f / (float)SPP);
            float r = fmaxf(at - A_gt[b], 0.0f);
            L_ol += r * r;
        }
        L_ol *= (1.0f / (float)B);
        out[0] = L_chd + L_mc + L_F + L_E + L_G + L_st + L_ol;
        g_done = 0;   // reset for next launch/replay
    }
}

extern "C" void kernel_launch(void* const* d_in, const int* in_sizes, int n_in,
                              void* d_out, int out_size) {
    (void)in_sizes; (void)n_in; (void)out_size;
    const float* pc_gt   = (const float*)d_in[0];
    const float* pc_pred = (const float*)d_in[1];
    const float* fffp    = (const float*)d_in[2];
    const float* A_gt    = (const float*)d_in[3];
    float* out = (float*)d_out;

    k_mega  <<<NBLK_C, 128>>>(pc_pred, pc_gt);
    k_finish<<<FB_T, FT>>>(fffp, A_gt, out);
}